// round 4
// baseline (speedup 1.0000x reference)
#include <cuda_runtime.h>
#include <cuda_bf16.h>
#include <math.h>
#include <stdint.h>

// ---------------------------------------------------------------------------
// MoE top-2/8: router -> permuted expert segments -> two tf32 mma.sync GEMMs.
// Raw-weight cp.async + in-register tf32 cvt; 3-stage pipeline, 1 sync/chunk.
// ---------------------------------------------------------------------------

#define BATCH      8192
#define D_MODEL    1024
#define HIDDEN     4096
#define NUM_CLS    1000
#define N2PAD      1024
#define NUM_EXP    8
#define TOPK       2
#define NPAIR      (BATCH * TOPK)
#define MAX_TILES  136
#define CAP        (MAX_TILES * 128)

// ---------------- scratch ---------------------------------------------------
__device__ float g_h[(size_t)CAP * HIDDEN];        // tf32-rounded hidden acts
__device__ float g_xR[(size_t)BATCH * D_MODEL];    // tf32-rounded x
__device__ float g_gates[BATCH * NUM_EXP];
__device__ int   g_topi[BATCH * TOPK];
__device__ int   g_pairExpert[NPAIR];
__device__ float g_pairGate[NPAIR];
__device__ int   g_counts[NUM_EXP];
__device__ int   g_segbase[NUM_EXP + 1];
__device__ int   g_cursor[NUM_EXP];
__device__ int   g_permToken[CAP];
__device__ int   g_permPair[CAP];
__device__ float g_permGate[CAP];

__device__ __forceinline__ float tf32r(float x) {
    uint32_t o; asm("cvt.rna.tf32.f32 %0, %1;" : "=r"(o) : "f"(x));
    return __uint_as_float(o);
}
__device__ __forceinline__ float gelu_exact(float v) {
    return 0.5f * v * (1.0f + erff(v * 0.70710678118654752f));
}
__device__ __forceinline__ uint32_t smem_u32(const void* p) {
    uint32_t a;
    asm("{ .reg .u64 t; cvta.to.shared.u64 t, %1; cvt.u32.u64 %0, t; }" : "=r"(a) : "l"(p));
    return a;
}

#define CPA16_SZ(dst, src, sz) asm volatile("cp.async.ca.shared.global [%0], [%1], 16, %2;" :: "r"(dst), "l"(src), "r"(sz))
#define CPA_COMMIT()           asm volatile("cp.async.commit_group;" ::: "memory")
#define CPA_WAIT1()            asm volatile("cp.async.wait_group 1;" ::: "memory")
#define CPA_WAIT0()            asm volatile("cp.async.wait_group 0;" ::: "memory")

__device__ __forceinline__ void mma_tf32(float* c, const uint32_t* a, const uint32_t* b) {
    asm volatile("mma.sync.aligned.m16n8k8.row.col.f32.tf32.tf32.f32 "
                 "{%0,%1,%2,%3}, {%4,%5,%6,%7}, {%8,%9}, {%0,%1,%2,%3};"
                 : "+f"(c[0]), "+f"(c[1]), "+f"(c[2]), "+f"(c[3])
                 : "r"(a[0]), "r"(a[1]), "r"(a[2]), "r"(a[3]), "r"(b[0]), "r"(b[1]));
}

// ---------------- prep: round x to tf32 -------------------------------------
__global__ void round_x(const float* __restrict__ x) {
    size_t n4 = (size_t)BATCH * D_MODEL / 4;
    for (size_t i = blockIdx.x * blockDim.x + threadIdx.x; i < n4; i += (size_t)gridDim.x * blockDim.x) {
        float4 v = ((const float4*)x)[i];
        v.x = tf32r(v.x); v.y = tf32r(v.y); v.z = tf32r(v.z); v.w = tf32r(v.w);
        ((float4*)g_xR)[i] = v;
    }
}

// ---------------- routing ----------------------------------------------------
__global__ void init_kernel() {
    int i = blockIdx.x * blockDim.x + threadIdx.x;
    if (i < CAP) { g_permToken[i] = -1; g_permPair[i] = -1; }
    if (i < NUM_EXP) g_counts[i] = 0;
}

__global__ void router_kernel(const float* __restrict__ x,
                              const float* __restrict__ Wg,
                              const float* __restrict__ bg) {
    int gwarp = (blockIdx.x * blockDim.x + threadIdx.x) >> 5;
    int lane  = threadIdx.x & 31;
    if (gwarp >= BATCH) return;
    const float* xr = x + (size_t)gwarp * D_MODEL;
    float acc[NUM_EXP];
#pragma unroll
    for (int e = 0; e < NUM_EXP; e++) acc[e] = 0.f;
    for (int k0 = lane * 4; k0 < D_MODEL; k0 += 128) {
        float4 xv = *(const float4*)(xr + k0);
        const float* xs = (const float*)&xv;
#pragma unroll
        for (int kk = 0; kk < 4; kk++) {
            const float4* wg = (const float4*)(Wg + (size_t)(k0 + kk) * NUM_EXP);
            float4 w0 = wg[0], w1 = wg[1];
            float xk = xs[kk];
            acc[0] += xk * w0.x; acc[1] += xk * w0.y;
            acc[2] += xk * w0.z; acc[3] += xk * w0.w;
            acc[4] += xk * w1.x; acc[5] += xk * w1.y;
            acc[6] += xk * w1.z; acc[7] += xk * w1.w;
        }
    }
#pragma unroll
    for (int off = 16; off; off >>= 1)
#pragma unroll
        for (int e = 0; e < NUM_EXP; e++)
            acc[e] += __shfl_xor_sync(0xFFFFFFFFu, acc[e], off);
    if (lane == 0) {
        float v[NUM_EXP];
#pragma unroll
        for (int e = 0; e < NUM_EXP; e++) v[e] = acc[e] + bg[e];
        int i1 = 0;
#pragma unroll
        for (int e = 1; e < NUM_EXP; e++) if (v[e] > v[i1]) i1 = e;
        int i2 = -1;
#pragma unroll
        for (int e = 0; e < NUM_EXP; e++)
            if (e != i1 && (i2 < 0 || v[e] > v[i2])) i2 = e;
        float e2 = expf(v[i2] - v[i1]);
        float g1 = 1.f / (1.f + e2), g2 = e2 / (1.f + e2);
#pragma unroll
        for (int e = 0; e < NUM_EXP; e++) g_gates[gwarp * NUM_EXP + e] = 0.f;
        g_gates[gwarp * NUM_EXP + i1] = g1;
        g_gates[gwarp * NUM_EXP + i2] = g2;
        g_topi[gwarp * TOPK + 0] = i1;
        g_topi[gwarp * TOPK + 1] = i2;
        g_pairExpert[gwarp * TOPK + 0] = i1;
        g_pairExpert[gwarp * TOPK + 1] = i2;
        g_pairGate[gwarp * TOPK + 0] = g1;
        g_pairGate[gwarp * TOPK + 1] = g2;
        atomicAdd(&g_counts[i1], 1);
        atomicAdd(&g_counts[i2], 1);
    }
}

__global__ void scan_kernel() {
    int base = 0;
#pragma unroll
    for (int e = 0; e < NUM_EXP; e++) {
        g_segbase[e] = base;
        g_cursor[e]  = base;
        base += ((g_counts[e] + 127) >> 7) << 7;
    }
    g_segbase[NUM_EXP] = base;
}

__global__ void scatter_kernel() {
    int p = blockIdx.x * blockDim.x + threadIdx.x;
    if (p >= NPAIR) return;
    int e = g_pairExpert[p];
    int pos = atomicAdd(&g_cursor[e], 1);
    g_permToken[pos] = p >> 1;
    g_permPair[pos]  = p;
    g_permGate[pos]  = g_pairGate[p];
}

// ---------------- tf32 mma GEMMs --------------------------------------------
// CTA: 256 thr (8 warps 2Mx4N), tile 128x128, BK=32, 3-stage cp.async pipeline.
#define AS_STRIDE 36
#define BS_STRIDE 136
#define AS_BYTES  (128 * AS_STRIDE * 4)            // 18432
#define BS_BYTES  (32 * BS_STRIDE * 4)             // 17408
#define STAGE_B   (AS_BYTES + BS_BYTES)            // 35840
#define NSTAGE    3
#define SMEM_TOT  (NSTAGE * STAGE_B)               // 107520

struct TileCtx {
    uint32_t aDst[NSTAGE], bDst[NSTAGE];
    const float* aSrc;
    const float* bSrc;
    const float* bSafe;         // fallback addr for size-0 cp.async
    int bStrideN;
    uint32_t aSz;
    uint32_t bSz[4];
};

__device__ __forceinline__ void issue_chunk(const TileCtx& c, int buf, int kt) {
#pragma unroll
    for (int j = 0; j < 4; j++)
        CPA16_SZ(c.aDst[buf] + j * 16, c.aSrc + kt + j * 4, c.aSz);
#pragma unroll
    for (int j = 0; j < 4; j++) {
        const float* s = c.bSz[j] ? (c.bSrc + (size_t)kt * c.bStrideN + j * 4) : c.bSafe;
        CPA16_SZ(c.bDst[buf] + j * 16, s, c.bSz[j]);
    }
    CPA_COMMIT();
}

template<bool CVTB>
__device__ __forceinline__ void mma_tile(const float* As, const float* Bs,
                                         int wr, int wc, int gid, int tig,
                                         float c[4][4][4]) {
#pragma unroll
    for (int ks = 0; ks < 4; ks++) {
        uint32_t b[4][2];
#pragma unroll
        for (int ni = 0; ni < 4; ni++) {
            int col = wc + ni * 8 + gid;
            float b0 = Bs[(ks * 8 + tig) * BS_STRIDE + col];
            float b1 = Bs[(ks * 8 + tig + 4) * BS_STRIDE + col];
            if (CVTB) { b0 = tf32r(b0); b1 = tf32r(b1); }
            b[ni][0] = __float_as_uint(b0);
            b[ni][1] = __float_as_uint(b1);
        }
#pragma unroll
        for (int mi = 0; mi < 4; mi++) {
            int r0 = wr + mi * 16 + gid;
            uint32_t a[4];
            a[0] = __float_as_uint(As[r0 * AS_STRIDE + ks * 8 + tig]);
            a[1] = __float_as_uint(As[(r0 + 8) * AS_STRIDE + ks * 8 + tig]);
            a[2] = __float_as_uint(As[r0 * AS_STRIDE + ks * 8 + tig + 4]);
            a[3] = __float_as_uint(As[(r0 + 8) * AS_STRIDE + ks * 8 + tig + 4]);
#pragma unroll
            for (int ni = 0; ni < 4; ni++) mma_tf32(c[mi][ni], a, b[ni]);
        }
    }
}

__device__ __forceinline__ void setup_ctx(TileCtx& c, char* smem, int tid) {
    uint32_t sb = smem_u32(smem);
    int am = tid >> 1, ak = (tid & 1) * 16;
    int bk = tid >> 3, bn = (tid & 7) * 16;
#pragma unroll
    for (int s = 0; s < NSTAGE; s++) {
        c.aDst[s] = sb + s * STAGE_B + (am * AS_STRIDE + ak) * 4;
        c.bDst[s] = sb + s * STAGE_B + AS_BYTES + (bk * BS_STRIDE + bn) * 4;
    }
    c.aSz = 16;
#pragma unroll
    for (int j = 0; j < 4; j++) c.bSz[j] = 16;
}

template<bool CVTB>
__device__ __forceinline__ void gemm_mainloop(const TileCtx& ctx, char* smem, int NIT,
                                              int wr, int wc, int gid, int tig,
                                              float c[4][4][4]) {
    issue_chunk(ctx, 0, 0);
    issue_chunk(ctx, 1, 32);
    for (int it = 0; it < NIT; ++it) {
        if (it + 1 < NIT) CPA_WAIT1(); else CPA_WAIT0();
        __syncthreads();
        if (it + 2 < NIT) issue_chunk(ctx, (it + 2) % NSTAGE, (it + 2) * 32);
        const int buf = it % NSTAGE;
        mma_tile<CVTB>((const float*)(smem + buf * STAGE_B),
                       (const float*)(smem + buf * STAGE_B + AS_BYTES),
                       wr, wc, gid, tig, c);
    }
}

__global__ __launch_bounds__(256, 2)
void gemm1_mma(const float* __restrict__ W1, const float* __restrict__ b1) {
    extern __shared__ __align__(16) char smem[];
    const int tid = threadIdx.x, wid = tid >> 5, lane = tid & 31;
    const int rowBase = blockIdx.x * 128, nBase = blockIdx.y * 128;
    if (rowBase >= g_segbase[NUM_EXP]) return;
    int expert = 0;
#pragma unroll
    for (int i = 1; i < NUM_EXP; i++) if (g_segbase[i] <= rowBase) expert = i;

    TileCtx ctx; setup_ctx(ctx, smem, tid);
    const int am = tid >> 1, ak = (tid & 1) * 16;
    const int bk = tid >> 3, bn = (tid & 7) * 16;
    const int tok = g_permToken[rowBase + am];
    ctx.aSrc = g_xR + (size_t)(tok < 0 ? 0 : tok) * D_MODEL + ak;
    ctx.aSz  = tok < 0 ? 0u : 16u;
    ctx.bSrc = W1 + (size_t)expert * D_MODEL * HIDDEN + (size_t)bk * HIDDEN + nBase + bn;
    ctx.bSafe = ctx.bSrc;
    ctx.bStrideN = HIDDEN;

    const int gid = lane >> 2, tig = lane & 3;
    const int wr = (wid >> 2) * 64, wc = (wid & 3) * 32;
    float c[4][4][4];
#pragma unroll
    for (int mi = 0; mi < 4; mi++)
#pragma unroll
        for (int ni = 0; ni < 4; ni++)
#pragma unroll
            for (int q = 0; q < 4; q++) c[mi][ni][q] = 0.f;

    gemm_mainloop<true>(ctx, smem, D_MODEL / 32, wr, wc, gid, tig, c);

    const float* bb = b1 + (size_t)expert * HIDDEN + nBase;
#pragma unroll
    for (int mi = 0; mi < 4; mi++) {
        int r0 = rowBase + wr + mi * 16 + gid;
#pragma unroll
        for (int ni = 0; ni < 4; ni++) {
            int col = wc + ni * 8 + tig * 2;
            float bias0 = __ldg(bb + col), bias1 = __ldg(bb + col + 1);
            float2 v0, v1;
            v0.x = tf32r(gelu_exact(c[mi][ni][0] + bias0));
            v0.y = tf32r(gelu_exact(c[mi][ni][1] + bias1));
            v1.x = tf32r(gelu_exact(c[mi][ni][2] + bias0));
            v1.y = tf32r(gelu_exact(c[mi][ni][3] + bias1));
            *(float2*)(g_h + (size_t)r0 * HIDDEN + nBase + col) = v0;
            *(float2*)(g_h + (size_t)(r0 + 8) * HIDDEN + nBase + col) = v1;
        }
    }
}

__global__ __launch_bounds__(256, 2)
void gemm2_mma(const float* __restrict__ W2, const float* __restrict__ b2,
               float* __restrict__ out) {
    extern __shared__ __align__(16) char smem[];
    const int tid = threadIdx.x, wid = tid >> 5, lane = tid & 31;
    const int rowBase = blockIdx.x * 128, nBase = blockIdx.y * 128;
    if (rowBase >= g_segbase[NUM_EXP]) return;
    int expert = 0;
#pragma unroll
    for (int i = 1; i < NUM_EXP; i++) if (g_segbase[i] <= rowBase) expert = i;

    TileCtx ctx; setup_ctx(ctx, smem, tid);
    const int am = tid >> 1, ak = (tid & 1) * 16;
    const int bk = tid >> 3, bn = (tid & 7) * 16;
    ctx.aSrc = g_h + (size_t)(rowBase + am) * HIDDEN + ak;
    const float* w2e = W2 + (size_t)expert * HIDDEN * NUM_CLS;
    ctx.bSrc = w2e + (size_t)bk * NUM_CLS + nBase + bn;
    ctx.bSafe = w2e;
    ctx.bStrideN = NUM_CLS;
#pragma unroll
    for (int j = 0; j < 4; j++) {
        int col0 = nBase + bn + j * 4;
        int rem = (NUM_CLS - col0) * 4;
        ctx.bSz[j] = rem <= 0 ? 0u : (rem >= 16 ? 16u : (uint32_t)rem);
    }

    const int gid = lane >> 2, tig = lane & 3;
    const int wr = (wid >> 2) * 64, wc = (wid & 3) * 32;
    float c[4][4][4];
#pragma unroll
    for (int mi = 0; mi < 4; mi++)
#pragma unroll
        for (int ni = 0; ni < 4; ni++)
#pragma unroll
            for (int q = 0; q < 4; q++) c[mi][ni][q] = 0.f;

    gemm_mainloop<true>(ctx, smem, HIDDEN / 32, wr, wc, gid, tig, c);

    const float* bb = b2 + (size_t)expert * NUM_CLS;
#pragma unroll
    for (int mi = 0; mi < 4; mi++) {
        int r0 = rowBase + wr + mi * 16 + gid;
#pragma unroll
        for (int half = 0; half < 2; half++) {
            int r = r0 + half * 8;
            int pair = g_permPair[r];
            if (pair < 0) continue;
            float gate = g_permGate[r];
            float* orow = out + (size_t)(pair >> 1) * NUM_CLS;
#pragma unroll
            for (int ni = 0; ni < 4; ni++) {
                int col = nBase + wc + ni * 8 + tig * 2;
                if (col < NUM_CLS)
                    atomicAdd(orow + col, gate * (c[mi][ni][half * 2 + 0] + __ldg(bb + col)));
                if (col + 1 < NUM_CLS)
                    atomicAdd(orow + col + 1, gate * (c[mi][ni][half * 2 + 1] + __ldg(bb + col + 1)));
            }
        }
    }
}

// ---------------- tail -------------------------------------------------------
__global__ void tail_kernel(float* __restrict__ out, int out_size) {
    int i = blockIdx.x * blockDim.x + threadIdx.x;
    const int OUT0 = BATCH * NUM_CLS;
    if (out_size >= OUT0 + BATCH * NUM_EXP) {
        if (i < BATCH * NUM_EXP)
            out[OUT0 + i] = g_gates[i];
        if (out_size >= OUT0 + BATCH * NUM_EXP + BATCH * TOPK && i < BATCH * TOPK)
            out[OUT0 + BATCH * NUM_EXP + i] = (float)g_topi[i];
    }
}

// ---------------------------------------------------------------------------
extern "C" void kernel_launch(void* const* d_in, const int* in_sizes, int n_in,
                              void* d_out, int out_size) {
    const float* x  = (const float*)d_in[0];
    const float* Wg = (const float*)d_in[1];
    const float* bg = (const float*)d_in[2];
    const float* W1 = (const float*)d_in[3];
    const float* b1 = (const float*)d_in[4];
    const float* W2 = (const float*)d_in[5];
    const float* b2 = (const float*)d_in[6];
    float* out = (float*)d_out;

    cudaFuncSetAttribute(gemm1_mma, cudaFuncAttributeMaxDynamicSharedMemorySize, SMEM_TOT);
    cudaFuncSetAttribute(gemm2_mma, cudaFuncAttributeMaxDynamicSharedMemorySize, SMEM_TOT);

    cudaMemsetAsync(d_out, 0, (size_t)out_size * sizeof(float));
    init_kernel<<<(CAP + 255) / 256, 256>>>();
    round_x<<<512, 256>>>(x);
    router_kernel<<<BATCH / 8, 256>>>(x, Wg, bg);
    scan_kernel<<<1, 1>>>();
    scatter_kernel<<<(NPAIR + 255) / 256, 256>>>();
    gemm1_mma<<<dim3(MAX_TILES, HIDDEN / 128), 256, SMEM_TOT>>>(W1, b1);
    gemm2_mma<<<dim3(MAX_TILES, N2PAD / 128), 256, SMEM_TOT>>>(W2, b2, out);
    tail_kernel<<<(BATCH * NUM_EXP + 255) / 256, 256>>>(out, out_size);
}